// round 14
// baseline (speedup 1.0000x reference)
#include <cuda_runtime.h>
#include <cuda_bf16.h>
#include <math.h>
#include <stdint.h>

#define K_CODES 2048
#define DDIM    512
#define N_ROWS  16384
#define QN      8388608
#define OUT_LOSS 0
#define OUT_Q    1
#define OUT_PERP (1+QN)
#define OUT_IDX  (2+QN)

#define BM 64
#define NPANEL 16
#define NCH 8
/* smem byte offsets */
#define SA    0                 /* 64 x 1040 = 66560 */
#define SB0   66560             /* 128 x 144 = 18432 */
#define SB1   84992
#define SWSQ  103424
#define SFSQ  103936
#define SIDX  104192
#define SRED  104960
#define SMEM_BYTES 104992
#define SCD   SB0               /* 64*24*4 = 6144, after B dead */
#define SCI   72704

__device__ __nv_bfloat16 g_xhb[(size_t)N_ROWS * DDIM];
__device__ __nv_bfloat16 g_whb[(size_t)K_CODES * DDIM];
__device__ float g_xt[(size_t)N_ROWS * DDIM];
__device__ float g_wsq[K_CODES];
__device__ float g_fsq[N_ROWS];
__device__ int   g_counts[K_CODES];
__device__ float g_partials[256];

__device__ __forceinline__ uint32_t smem_u32(const void* p) {
    uint32_t a;
    asm("{ .reg .u64 t; cvta.to.shared.u64 t, %1; cvt.u32.u64 %0, t; }" : "=r"(a) : "l"(p));
    return a;
}
__device__ __forceinline__ void ldsm4(uint32_t a, uint32_t& r0, uint32_t& r1, uint32_t& r2, uint32_t& r3) {
    asm volatile("ldmatrix.sync.aligned.m8n8.x4.shared.b16 {%0,%1,%2,%3}, [%4];"
        : "=r"(r0), "=r"(r1), "=r"(r2), "=r"(r3) : "r"(a));
}
__device__ __forceinline__ void mma16816(float* c, uint32_t a0, uint32_t a1, uint32_t a2, uint32_t a3,
                                         uint32_t b0, uint32_t b1) {
    asm volatile("mma.sync.aligned.m16n8k16.row.col.f32.bf16.bf16.f32 "
        "{%0,%1,%2,%3},{%4,%5,%6,%7},{%8,%9},{%0,%1,%2,%3};"
        : "+f"(c[0]), "+f"(c[1]), "+f"(c[2]), "+f"(c[3])
        : "r"(a0), "r"(a1), "r"(a2), "r"(a3), "r"(b0), "r"(b1));
}
__device__ __forceinline__ void ins3(float* td, int* ti, float v, int c) {
    if (v < td[2]) {
        td[2] = v; ti[2] = c;
        if (td[2] < td[1]) { float a = td[2]; td[2] = td[1]; td[1] = a; int b = ti[2]; ti[2] = ti[1]; ti[1] = b; }
        if (td[1] < td[0]) { float a = td[1]; td[1] = td[0]; td[0] = a; int b = ti[1]; ti[1] = ti[0]; ti[0] = b; }
    }
}

__global__ void init_counts() {
    int i = blockIdx.x * blockDim.x + threadIdx.x;
    if (i < K_CODES) g_counts[i] = 0;
}
__global__ void conv_w(const float* __restrict__ W) {
    int warp = (blockIdx.x * blockDim.x + threadIdx.x) >> 5, lane = threadIdx.x & 31;
    if (warp >= K_CODES) return;
    const float* row = W + (size_t)warp * DDIM;
    float s = 0.f;
    for (int d = lane; d < DDIM; d += 32) {
        float v = row[d];
        s += v * v;
        g_whb[(size_t)warp * DDIM + d] = __float2bfloat16_rn(v);
    }
    for (int o = 16; o > 0; o >>= 1) s += __shfl_xor_sync(0xffffffffu, s, o);
    if (lane == 0) g_wsq[warp] = s;
}
__global__ void fsq_kernel(const float* __restrict__ x) {
    int b = blockIdx.x, t = threadIdx.x;
    const float* p = x + (size_t)b * DDIM * 256 + t;
    float s = 0.f;
    for (int d = 0; d < DDIM; d++) { float v = p[(size_t)d * 256]; s += v * v; }
    g_fsq[b * 256 + t] = s;
}
__global__ void conv_x(const float* __restrict__ x) {
    __shared__ float sh[64][65];
    int b = blockIdx.z, d0 = blockIdx.y * 64, t0 = blockIdx.x * 64, tid = threadIdx.x;
    #pragma unroll
    for (int i = 0; i < 16; i++) {
        int lin = i * 256 + tid, dd = lin >> 6, tt = lin & 63;
        sh[dd][tt] = x[((size_t)b * DDIM + d0 + dd) * 256 + t0 + tt];
    }
    __syncthreads();
    #pragma unroll
    for (int i = 0; i < 16; i++) {
        int lin = i * 256 + tid, nn = lin >> 6, dd = lin & 63;
        float v = sh[dd][nn];
        size_t o = (size_t)(b * 256 + t0 + nn) * DDIM + d0 + dd;
        g_xt[o] = v;
        g_xhb[o] = __float2bfloat16_rn(v);
    }
}

__global__ __launch_bounds__(256, 2)
void vq_main(const float* __restrict__ x, const float* __restrict__ W,
             float* __restrict__ out) {
    extern __shared__ char sm[];
    const uint32_t smb = smem_u32(sm);
    const int tid = threadIdx.x, wid = tid >> 5, lane = tid & 31;
    const int mt = wid >> 1, nh = wid & 1, m0 = mt * 16;
    const int gr0 = blockIdx.x * BM;
    float* cd_s = (float*)(sm + SCD);
    int*   ci_s = (int*)(sm + SCI);
    float* wsq_s = (float*)(sm + SWSQ);
    float* fsq_s = (float*)(sm + SFSQ);
    int*   idx_s = (int*)(sm + SIDX);
    float* red_s = (float*)(sm + SRED);

    if (tid < BM) fsq_s[tid] = g_fsq[gr0 + tid];
    {   /* resident A tile: 64 x 512 bf16, stride 1040B */
        const int4* src = (const int4*)g_xhb;
        for (int i = tid; i < 4096; i += 256) {
            int row = i >> 6, seg = i & 63;
            *(int4*)(sm + SA + row * 1040 + seg * 16) = src[(size_t)(gr0 + row) * 64 + seg];
        }
    }
    const uint32_t aBase = smb + SA +
        (uint32_t)((m0 + ((lane >> 3) & 1) * 8 + (lane & 7)) * 1040 + ((lane >> 4) & 1) * 16);
    const uint32_t bOff =
        (uint32_t)(((((lane >> 4) & 1) * 8) + (lane & 7)) * 144 + ((lane >> 3) & 1) * 16);
    const int bc = tid >> 1, bh = tid & 1;
    const int lq = lane & 3;
    const int4* wsrc = (const int4*)g_whb;

    float td0[3], td1[3]; int ti0[3], ti1[3];
    #pragma unroll
    for (int s = 0; s < 3; s++) {
        td0[s] = INFINITY; td1[s] = INFINITY; ti0[s] = 0; ti1[s] = 0;
    }

    for (int p = 0; p < NPANEL; p++) {
        const int c0 = p * 128;
        __syncthreads();
        if (tid < 128) wsq_s[tid] = g_wsq[c0 + tid];
        #pragma unroll
        for (int j = 0; j < 4; j++)
            *(int4*)(sm + SB0 + bc * 144 + bh * 64 + j * 16) = wsrc[(size_t)(c0 + bc) * 64 + bh * 4 + j];
        __syncthreads();

        float acc[32];
        #pragma unroll
        for (int i = 0; i < 32; i++) acc[i] = 0.f;

        for (int kc = 0; kc < NCH; kc++) {
            int4 pf[4];
            if (kc < NCH - 1)
                #pragma unroll
                for (int j = 0; j < 4; j++)
                    pf[j] = wsrc[(size_t)(c0 + bc) * 64 + (kc + 1) * 8 + bh * 4 + j];
            const uint32_t bufB = smb + ((kc & 1) ? SB1 : SB0);
            #pragma unroll
            for (int k16 = 0; k16 < 4; k16++) {
                uint32_t a0, a1, a2, a3;
                ldsm4(aBase + kc * 128 + k16 * 32, a0, a1, a2, a3);
                #pragma unroll
                for (int n16 = 0; n16 < 4; n16++) {
                    uint32_t b0, b1, b2, b3;
                    ldsm4(bufB + (nh * 4 + n16) * 2304 + bOff + k16 * 32, b0, b1, b2, b3);
                    mma16816(acc + (n16 * 2 + 0) * 4, a0, a1, a2, a3, b0, b1);
                    mma16816(acc + (n16 * 2 + 1) * 4, a0, a1, a2, a3, b2, b3);
                }
            }
            __syncthreads();
            if (kc < NCH - 1) {
                char* dst = sm + (((kc + 1) & 1) ? SB1 : SB0);
                #pragma unroll
                for (int j = 0; j < 4; j++)
                    *(int4*)(dst + bc * 144 + bh * 64 + j * 16) = pf[j];
                __syncthreads();
            }
        }
        /* in-register screening: per-thread top-3 per row */
        #pragma unroll
        for (int gg = 0; gg < 8; gg++) {
            const int c = nh * 64 + (gg >> 1) * 16 + (gg & 1) * 8 + lq * 2;
            const float w0 = wsq_s[c], w1 = wsq_s[c + 1];
            const int code = c0 + c;
            ins3(td0, ti0, fmaf(-2.f, acc[gg * 4 + 0], w0), code);
            ins3(td0, ti0, fmaf(-2.f, acc[gg * 4 + 1], w1), code + 1);
            ins3(td1, ti1, fmaf(-2.f, acc[gg * 4 + 2], w0), code);
            ins3(td1, ti1, fmaf(-2.f, acc[gg * 4 + 3], w1), code + 1);
        }
    }
    __syncthreads();   /* B buffers dead; reuse as candidate store */
    {   /* dump 24 candidates per row (2 warps x 4 lanes x 3) */
        const int r0 = m0 + (lane >> 2);
        const int slot = (nh * 4 + lq) * 3;
        #pragma unroll
        for (int s = 0; s < 3; s++) {
            cd_s[r0 * 24 + slot + s] = td0[s]; ci_s[r0 * 24 + slot + s] = ti0[s];
            cd_s[(r0 + 8) * 24 + slot + s] = td1[s]; ci_s[(r0 + 8) * 24 + slot + s] = ti1[s];
        }
    }
    __syncthreads();

    /* exact rescore: same FFMA chain/order as R1 -> bitwise identical dists */
    #pragma unroll 1
    for (int q = 0; q < 6; q++) {
        const int pair = q * 256 + tid, r = pair / 24;
        const int ci = ci_s[pair];
        const float4* wp = (const float4*)(W + (size_t)ci * DDIM);
        const float4* xp = (const float4*)(g_xt + (size_t)(gr0 + r) * DDIM);
        float s = 0.f;
        #pragma unroll 8
        for (int d4 = 0; d4 < 128; d4++) {
            float4 a = xp[d4], b = wp[d4];
            s = fmaf(a.x, b.x, s); s = fmaf(a.y, b.y, s);
            s = fmaf(a.z, b.z, s); s = fmaf(a.w, b.w, s);
        }
        cd_s[pair] = __fadd_rn(__fadd_rn(fsq_s[r], g_wsq[ci]), -__fmul_rn(2.0f, s));
    }
    __syncthreads();

    if (tid < BM) {
        float b0 = INFINITY, b1 = INFINITY, b2 = INFINITY;
        int i0 = 0x7fffffff, i1 = 0x7fffffff, i2 = 0x7fffffff;
        #pragma unroll
        for (int s = 0; s < 24; s++) {
            float d = cd_s[tid * 24 + s]; int c = ci_s[tid * 24 + s];
            if (d < b0 || (d == b0 && c < i0)) {
                b2 = b1; i2 = i1; b1 = b0; i1 = i0; b0 = d; i0 = c;
            } else if (d < b1 || (d == b1 && c < i1)) {
                b2 = b1; i2 = i1; b1 = d; i1 = c;
            } else if (d < b2 || (d == b2 && c < i2)) {
                b2 = d; i2 = c;
            }
        }
        idx_s[tid * 3 + 0] = i0; idx_s[tid * 3 + 1] = i1; idx_s[tid * 3 + 2] = i2;
        atomicAdd(&g_counts[i0], 1);
        atomicAdd(&g_counts[i1], 1);
        atomicAdd(&g_counts[i2], 1);
        out[OUT_IDX + gr0 + tid] = (float)i2;
    }
    __syncthreads();

    /* quantized output + MSE */
    const int bq = gr0 >> 8, t0 = gr0 & 255;
    float* q_s = (float*)(sm + SA);   /* 32 x 64 */
    float mse = 0.f;
    const int r = tid & 63, dh = tid >> 6;   /* 0..3 */
    const int j0 = idx_s[r * 3 + 0], j1 = idx_s[r * 3 + 1], j2 = idx_s[r * 3 + 2];
    for (int dc = 0; dc < 16; dc++) {
        const int d0 = dc * 32 + dh * 8;
        #pragma unroll
        for (int q4 = 0; q4 < 2; q4++) {
            float4 a = *(const float4*)(W + (size_t)j0 * DDIM + d0 + q4 * 4);
            float4 bb = *(const float4*)(W + (size_t)j1 * DDIM + d0 + q4 * 4);
            float4 cc = *(const float4*)(W + (size_t)j2 * DDIM + d0 + q4 * 4);
            int dl = dh * 8 + q4 * 4;
            q_s[(dl + 0) * 64 + r] = (a.x + bb.x + cc.x) * (1.0f / 3.0f);
            q_s[(dl + 1) * 64 + r] = (a.y + bb.y + cc.y) * (1.0f / 3.0f);
            q_s[(dl + 2) * 64 + r] = (a.z + bb.z + cc.z) * (1.0f / 3.0f);
            q_s[(dl + 3) * 64 + r] = (a.w + bb.w + cc.w) * (1.0f / 3.0f);
        }
        __syncthreads();
        #pragma unroll
        for (int i = 0; i < 8; i++) {
            int lin = i * 256 + tid, dl = lin >> 6, rr = lin & 63;
            int d = dc * 32 + dl;
            size_t go = (size_t)(bq * DDIM + d) * 256 + t0 + rr;
            float qv = q_s[dl * 64 + rr];
            out[OUT_Q + go] = qv;
            float df = qv - x[go];
            mse += df * df;
        }
        __syncthreads();
    }
    for (int o = 16; o > 0; o >>= 1) mse += __shfl_xor_sync(0xffffffffu, mse, o);
    if (lane == 0) red_s[wid] = mse;
    __syncthreads();
    if (tid == 0) {
        float s = 0.f;
        #pragma unroll
        for (int i = 0; i < 8; i++) s += red_s[i];
        g_partials[blockIdx.x] = s;
    }
}

__global__ void finalize_kernel(float* __restrict__ out) {
    __shared__ float red[256];
    int tid = threadIdx.x;
    red[tid] = g_partials[tid];
    __syncthreads();
    for (int s = 128; s > 0; s >>= 1) {
        if (tid < s) red[tid] += red[tid + s];
        __syncthreads();
    }
    if (tid == 0) out[OUT_LOSS] = 1.25f * (red[0] / (float)QN);
    __syncthreads();
    float e = 0.f;
    for (int k = tid; k < K_CODES; k += 256) {
        float pr = (float)g_counts[k] * (1.0f / (float)N_ROWS);
        e += pr * logf(pr + 1e-10f);
    }
    red[tid] = e;
    __syncthreads();
    for (int s = 128; s > 0; s >>= 1) {
        if (tid < s) red[tid] += red[tid + s];
        __syncthreads();
    }
    if (tid == 0) out[OUT_PERP] = expf(-red[0]);
}

extern "C" void kernel_launch(void* const* d_in, const int* in_sizes, int n_in,
                              void* d_out, int out_size) {
    const float* x = (const float*)d_in[0];
    const float* W = (const float*)d_in[1];
    float* out = (float*)d_out;
    (void)in_sizes; (void)n_in; (void)out_size;
    cudaFuncSetAttribute(vq_main, cudaFuncAttributeMaxDynamicSharedMemorySize, SMEM_BYTES);
    init_counts<<<8, 256>>>();
    conv_w<<<256, 256>>>(W);
    fsq_kernel<<<64, 256>>>(x);
    conv_x<<<dim3(4, 8, 64), 256>>>(x);
    vq_main<<<256, 256, SMEM_BYTES>>>(x, W, out);
    finalize_kernel<<<1, 256>>>(out);
}

// round 15
// speedup vs baseline: 1.3028x; 1.3028x over previous
#include <cuda_runtime.h>
#include <cuda_bf16.h>
#include <math.h>
#include <stdint.h>

#define K_CODES 2048
#define DDIM    512
#define N_ROWS  16384
#define QN      8388608
#define OUT_LOSS 0
#define OUT_Q    1
#define OUT_PERP (1+QN)
#define OUT_IDX  (2+QN)

#define BM 128
#define NPANEL 16
#define NCH 8
/* smem byte offsets */
#define SA    0                    /* 128 x 1040 = 133120 */
#define SB    133120               /* 3 stages x 18432 */
#define SBSTRIDE 18432
#define SWSQ  188416
#define SFSQ  188928
#define SIDX  189440
#define SRED  190976
#define SMEM_BYTES 191040
#define SCD   133120               /* overlay stage 0 after GEMM */
#define SCI   141312

__device__ __nv_bfloat16 g_xhb[(size_t)N_ROWS * DDIM];
__device__ __nv_bfloat16 g_whb[(size_t)K_CODES * DDIM];
__device__ float g_xt[(size_t)N_ROWS * DDIM];
__device__ float g_wsq[K_CODES];
__device__ float g_fsq[N_ROWS];
__device__ int   g_counts[K_CODES];
__device__ float g_partials[128];

__device__ __forceinline__ uint32_t smem_u32(const void* p) {
    uint32_t a;
    asm("{ .reg .u64 t; cvta.to.shared.u64 t, %1; cvt.u32.u64 %0, t; }" : "=r"(a) : "l"(p));
    return a;
}
__device__ __forceinline__ void cp16(uint32_t dst, const void* src) {
    asm volatile("cp.async.cg.shared.global [%0], [%1], 16;" :: "r"(dst), "l"(src));
}
#define CP_COMMIT() asm volatile("cp.async.commit_group;")
#define CP_WAIT1()  asm volatile("cp.async.wait_group 1;")
__device__ __forceinline__ void ldsm4(uint32_t a, uint32_t& r0, uint32_t& r1, uint32_t& r2, uint32_t& r3) {
    asm volatile("ldmatrix.sync.aligned.m8n8.x4.shared.b16 {%0,%1,%2,%3}, [%4];"
        : "=r"(r0), "=r"(r1), "=r"(r2), "=r"(r3) : "r"(a));
}
__device__ __forceinline__ void mma16816(float* c, uint32_t a0, uint32_t a1, uint32_t a2, uint32_t a3,
                                         uint32_t b0, uint32_t b1) {
    asm volatile("mma.sync.aligned.m16n8k16.row.col.f32.bf16.bf16.f32 "
        "{%0,%1,%2,%3},{%4,%5,%6,%7},{%8,%9},{%0,%1,%2,%3};"
        : "+f"(c[0]), "+f"(c[1]), "+f"(c[2]), "+f"(c[3])
        : "r"(a0), "r"(a1), "r"(a2), "r"(a3), "r"(b0), "r"(b1));
}
__device__ __forceinline__ void ins4(float* td, int* ti, float v, int c) {
    if (v < td[3]) {
        td[3] = v; ti[3] = c;
        if (td[3] < td[2]) { float a = td[3]; td[3] = td[2]; td[2] = a; int b = ti[3]; ti[3] = ti[2]; ti[2] = b; }
        if (td[2] < td[1]) { float a = td[2]; td[2] = td[1]; td[1] = a; int b = ti[2]; ti[2] = ti[1]; ti[1] = b; }
        if (td[1] < td[0]) { float a = td[1]; td[1] = td[0]; td[0] = a; int b = ti[1]; ti[1] = ti[0]; ti[0] = b; }
    }
}

/* conv W -> bf16 + wsq + zero counts */
__global__ void conv_w(const float* __restrict__ W) {
    if (threadIdx.x < 8 && blockIdx.x < 1) {
        for (int i = threadIdx.x; i < K_CODES; i += 8) g_counts[i] = 0;
    }
    int warp = (blockIdx.x * blockDim.x + threadIdx.x) >> 5, lane = threadIdx.x & 31;
    if (warp >= K_CODES) return;
    const float* row = W + (size_t)warp * DDIM;
    float s = 0.f;
    for (int d = lane; d < DDIM; d += 32) {
        float v = row[d];
        s += v * v;
        g_whb[(size_t)warp * DDIM + d] = __float2bfloat16_rn(v);
    }
    for (int o = 16; o > 0; o >>= 1) s += __shfl_xor_sync(0xffffffffu, s, o);
    if (lane == 0) g_wsq[warp] = s;
}
__global__ void fsq_kernel(const float* __restrict__ x) {
    int b = blockIdx.x, t = threadIdx.x;
    const float* p = x + (size_t)b * DDIM * 256 + t;
    float s = 0.f;
    for (int d = 0; d < DDIM; d++) { float v = p[(size_t)d * 256]; s += v * v; }
    g_fsq[b * 256 + t] = s;
}
__global__ void conv_x(const float* __restrict__ x) {
    __shared__ float sh[64][65];
    int b = blockIdx.z, d0 = blockIdx.y * 64, t0 = blockIdx.x * 64, tid = threadIdx.x;
    #pragma unroll
    for (int i = 0; i < 16; i++) {
        int lin = i * 256 + tid, dd = lin >> 6, tt = lin & 63;
        sh[dd][tt] = x[((size_t)b * DDIM + d0 + dd) * 256 + t0 + tt];
    }
    __syncthreads();
    #pragma unroll
    for (int i = 0; i < 16; i++) {
        int lin = i * 256 + tid, nn = lin >> 6, dd = lin & 63;
        float v = sh[dd][nn];
        size_t o = (size_t)(b * 256 + t0 + nn) * DDIM + d0 + dd;
        g_xt[o] = v;
        g_xhb[o] = __float2bfloat16_rn(v);
    }
}

__global__ __launch_bounds__(256, 1)
void vq_main(const float* __restrict__ x, const float* __restrict__ W,
             float* __restrict__ out) {
    extern __shared__ char sm[];
    const uint32_t smb = smem_u32(sm);
    const int tid = threadIdx.x, wid = tid >> 5, lane = tid & 31;
    const int gr0 = blockIdx.x * BM, m0 = wid * 16;
    float* cd_s = (float*)(sm + SCD);
    int*   ci_s = (int*)(sm + SCI);
    float* wsq_s = (float*)(sm + SWSQ);
    float* fsq_s = (float*)(sm + SFSQ);
    int*   idx_s = (int*)(sm + SIDX);
    float* red_s = (float*)(sm + SRED);

    if (tid < BM) fsq_s[tid] = g_fsq[gr0 + tid];
    {   /* resident A tile: 128 x 512 bf16, stride 1040B */
        const int4* src = (const int4*)g_xhb;
        for (int i = tid; i < 8192; i += 256) {
            int row = i >> 6, seg = i & 63;
            *(int4*)(sm + SA + row * 1040 + seg * 16) = src[(size_t)(gr0 + row) * 64 + seg];
        }
    }
    const uint32_t aBase = smb + SA +
        (uint32_t)((m0 + ((lane >> 3) & 1) * 8 + (lane & 7)) * 1040 + ((lane >> 4) & 1) * 16);
    const uint32_t bOff =
        (uint32_t)(((((lane >> 4) & 1) * 8) + (lane & 7)) * 144 + ((lane >> 3) & 1) * 16);
    const int bc = tid >> 1, bh = tid & 1;
    const int lq = lane & 3;
    const int4* wsrc = (const int4*)g_whb;
    const uint32_t bDst = smb + SB + (uint32_t)(bc * 144 + bh * 64);

    float td0[4], td1[4]; int ti0[4], ti1[4];
    #pragma unroll
    for (int s = 0; s < 4; s++) {
        td0[s] = INFINITY; td1[s] = INFINITY; ti0[s] = 0; ti1[s] = 0;
    }

    for (int p = 0; p < NPANEL; p++) {
        const int c0 = p * 128;
        __syncthreads();     /* ring + wsq_s reuse safe; A resident */
        if (tid < 128) wsq_s[tid] = g_wsq[c0 + tid];
        /* prologue: chunks 0,1 -> stages 0,1 */
        const int4* srcRow = wsrc + (size_t)(c0 + bc) * 64 + bh * 4;
        #pragma unroll
        for (int j = 0; j < 4; j++) cp16(bDst + j * 16, srcRow + j);
        CP_COMMIT();
        #pragma unroll
        for (int j = 0; j < 4; j++) cp16(bDst + SBSTRIDE + j * 16, srcRow + 8 + j);
        CP_COMMIT();

        float acc[64];
        #pragma unroll
        for (int i = 0; i < 64; i++) acc[i] = 0.f;

        int st = 0, st2 = 2;
        for (int kc = 0; kc < NCH; kc++) {
            CP_WAIT1();
            __syncthreads();
            if (kc + 2 < NCH) {
                const int4* srcN = srcRow + (kc + 2) * 8;
                const uint32_t dstN = bDst + st2 * SBSTRIDE;
                #pragma unroll
                for (int j = 0; j < 4; j++) cp16(dstN + j * 16, srcN + j);
            }
            CP_COMMIT();
            const uint32_t bufB = smb + SB + st * SBSTRIDE;
            #pragma unroll
            for (int k16 = 0; k16 < 4; k16++) {
                uint32_t a0, a1, a2, a3;
                ldsm4(aBase + kc * 128 + k16 * 32, a0, a1, a2, a3);
                #pragma unroll
                for (int n16 = 0; n16 < 8; n16++) {
                    uint32_t b0, b1, b2, b3;
                    ldsm4(bufB + n16 * 2304 + bOff + k16 * 32, b0, b1, b2, b3);
                    mma16816(acc + (n16 * 2 + 0) * 4, a0, a1, a2, a3, b0, b1);
                    mma16816(acc + (n16 * 2 + 1) * 4, a0, a1, a2, a3, b2, b3);
                }
            }
            st = (st == 2) ? 0 : st + 1;
            st2 = (st2 == 2) ? 0 : st2 + 1;
        }
        /* in-register screening: per-thread top-4 per row over own columns */
        #pragma unroll
        for (int gg = 0; gg < 16; gg++) {
            const int c = (gg >> 3) * 64 + (gg & 7) * 8 + lq * 2;
            const float w0 = wsq_s[c], w1 = wsq_s[c + 1];
            const int code = c0 + c;
            ins4(td0, ti0, fmaf(-2.f, acc[gg * 4 + 0], w0), code);
            ins4(td0, ti0, fmaf(-2.f, acc[gg * 4 + 1], w1), code + 1);
            ins4(td1, ti1, fmaf(-2.f, acc[gg * 4 + 2], w0), code);
            ins4(td1, ti1, fmaf(-2.f, acc[gg * 4 + 3], w1), code + 1);
        }
    }
    __syncthreads();     /* B ring dead -> candidate store */
    {   /* dump 16 candidates per row (4 lanes x 4) */
        const int r0 = m0 + (lane >> 2);
        #pragma unroll
        for (int s = 0; s < 4; s++) {
            cd_s[r0 * 16 + lq * 4 + s] = td0[s]; ci_s[r0 * 16 + lq * 4 + s] = ti0[s];
            cd_s[(r0 + 8) * 16 + lq * 4 + s] = td1[s]; ci_s[(r0 + 8) * 16 + lq * 4 + s] = ti1[s];
        }
    }
    __syncthreads();

    /* exact rescore: same FFMA chain/order as R1 -> bitwise identical dists */
    #pragma unroll 1
    for (int q = 0; q < 8; q++) {
        const int pair = q * 256 + tid, r = pair >> 4;
        const int ci = ci_s[pair];
        const float4* wp = (const float4*)(W + (size_t)ci * DDIM);
        const float4* xp = (const float4*)(g_xt + (size_t)(gr0 + r) * DDIM);
        float s = 0.f;
        #pragma unroll 8
        for (int d4 = 0; d4 < 128; d4++) {
            float4 a = xp[d4], b = wp[d4];
            s = fmaf(a.x, b.x, s); s = fmaf(a.y, b.y, s);
            s = fmaf(a.z, b.z, s); s = fmaf(a.w, b.w, s);
        }
        cd_s[pair] = __fadd_rn(__fadd_rn(fsq_s[r], g_wsq[ci]), -__fmul_rn(2.0f, s));
    }
    __syncthreads();

    if (tid < BM) {
        float b0 = INFINITY, b1 = INFINITY, b2 = INFINITY;
        int i0 = 0x7fffffff, i1 = 0x7fffffff, i2 = 0x7fffffff;
        #pragma unroll
        for (int s = 0; s < 16; s++) {
            float d = cd_s[tid * 16 + s]; int c = ci_s[tid * 16 + s];
            if (d < b0 || (d == b0 && c < i0)) {
                b2 = b1; i2 = i1; b1 = b0; i1 = i0; b0 = d; i0 = c;
            } else if (d < b1 || (d == b1 && c < i1)) {
                b2 = b1; i2 = i1; b1 = d; i1 = c;
            } else if (d < b2 || (d == b2 && c < i2)) {
                b2 = d; i2 = c;
            }
        }
        idx_s[tid * 3 + 0] = i0; idx_s[tid * 3 + 1] = i1; idx_s[tid * 3 + 2] = i2;
        atomicAdd(&g_counts[i0], 1);
        atomicAdd(&g_counts[i1], 1);
        atomicAdd(&g_counts[i2], 1);
        out[OUT_IDX + gr0 + tid] = (float)i2;
    }
    __syncthreads();

    /* quantized output + MSE */
    const int bq = gr0 >> 8, t0 = gr0 & 255;
    float* q_s = (float*)(sm + SA);
    float mse = 0.f;
    const int r = tid & 127, dh = tid >> 7;
    const int j0 = idx_s[r * 3 + 0], j1 = idx_s[r * 3 + 1], j2 = idx_s[r * 3 + 2];
    for (int dc = 0; dc < 16; dc++) {
        const int d0 = dc * 32 + dh * 16;
        #pragma unroll
        for (int q4 = 0; q4 < 4; q4++) {
            float4 a = *(const float4*)(W + (size_t)j0 * DDIM + d0 + q4 * 4);
            float4 bb = *(const float4*)(W + (size_t)j1 * DDIM + d0 + q4 * 4);
            float4 cc = *(const float4*)(W + (size_t)j2 * DDIM + d0 + q4 * 4);
            int dl = dh * 16 + q4 * 4;
            q_s[(dl + 0) * 128 + r] = (a.x + bb.x + cc.x) * (1.0f / 3.0f);
            q_s[(dl + 1) * 128 + r] = (a.y + bb.y + cc.y) * (1.0f / 3.0f);
            q_s[(dl + 2) * 128 + r] = (a.z + bb.z + cc.z) * (1.0f / 3.0f);
            q_s[(dl + 3) * 128 + r] = (a.w + bb.w + cc.w) * (1.0f / 3.0f);
        }
        __syncthreads();
        #pragma unroll
        for (int i = 0; i < 16; i++) {
            int lin = i * 256 + tid, dl = lin >> 7, rr = lin & 127;
            int d = dc * 32 + dl;
            size_t go = (size_t)(bq * DDIM + d) * 256 + t0 + rr;
            float qv = q_s[dl * 128 + rr];
            out[OUT_Q + go] = qv;
            float df = qv - x[go];
            mse += df * df;
        }
        __syncthreads();
    }
    for (int o = 16; o > 0; o >>= 1) mse += __shfl_xor_sync(0xffffffffu, mse, o);
    if (lane == 0) red_s[wid] = mse;
    __syncthreads();
    if (tid == 0) {
        float s = 0.f;
        #pragma unroll
        for (int i = 0; i < 8; i++) s += red_s[i];
        g_partials[blockIdx.x] = s;
    }
}

__global__ void finalize_kernel(float* __restrict__ out) {
    __shared__ float red[256];
    int tid = threadIdx.x;
    red[tid] = (tid < 128) ? g_partials[tid] : 0.f;
    __syncthreads();
    for (int s = 128; s > 0; s >>= 1) {
        if (tid < s) red[tid] += red[tid + s];
        __syncthreads();
    }
    if (tid == 0) out[OUT_LOSS] = 1.25f * (red[0] / (float)QN);
    __syncthreads();
    float e = 0.f;
    for (int k = tid; k < K_CODES; k += 256) {
        float pr = (float)g_counts[k] * (1.0f / (float)N_ROWS);
        e += pr * logf(pr + 1e-10f);
    }
    red[tid] = e;
    __syncthreads();
    for (int s = 128; s > 0; s >>= 1) {
        if (tid < s) red[tid] += red[tid + s];
        __syncthreads();
    }
    if (tid == 0) out[OUT_PERP] = expf(-red[0]);
}

extern "C" void kernel_launch(void* const* d_in, const int* in_sizes, int n_in,
                              void* d_out, int out_size) {
    const float* x = (const float*)d_in[0];
    const float* W = (const float*)d_in[1];
    float* out = (float*)d_out;
    (void)in_sizes; (void)n_in; (void)out_size;
    cudaFuncSetAttribute(vq_main, cudaFuncAttributeMaxDynamicSharedMemorySize, SMEM_BYTES);
    conv_w<<<256, 256>>>(W);
    fsq_kernel<<<64, 256>>>(x);
    conv_x<<<dim3(4, 8, 64), 256>>>(x);
    vq_main<<<128, 256, SMEM_BYTES>>>(x, W, out);
    finalize_kernel<<<1, 256>>>(out);
}

// round 16
// speedup vs baseline: 1.5868x; 1.2180x over previous
#include <cuda_runtime.h>
#include <cuda_bf16.h>
#include <math.h>
#include <stdint.h>

#define K_CODES 2048
#define DDIM    512
#define N_ROWS  16384
#define QN      8388608
#define OUT_LOSS 0
#define OUT_Q    1
#define OUT_PERP (1+QN)
#define OUT_IDX  (2+QN)

#define BM 128
#define NPANEL 16
#define NCH 8
/* smem byte offsets */
#define SA    0                    /* 128 x 1040 = 133120 */
#define SB    133120               /* 3 stages x 18432 */
#define SBSTRIDE 18432
#define SWSQ  188416
#define SFSQ  188928
#define SIDX  189440
#define SRED  190976
#define SMEM_BYTES 191104
#define SCD   133120               /* overlay B ring after GEMM: 128*48*4 */
#define SCI   157696

__device__ __nv_bfloat16 g_xhb[(size_t)N_ROWS * DDIM];
__device__ __nv_bfloat16 g_whb[(size_t)K_CODES * DDIM];
__device__ float g_xt[(size_t)N_ROWS * DDIM];
__device__ float g_wsq[K_CODES];
__device__ float g_fsq[N_ROWS];
__device__ int   g_counts[K_CODES];
__device__ float g_partials[128];

__device__ __forceinline__ uint32_t smem_u32(const void* p) {
    uint32_t a;
    asm("{ .reg .u64 t; cvta.to.shared.u64 t, %1; cvt.u32.u64 %0, t; }" : "=r"(a) : "l"(p));
    return a;
}
__device__ __forceinline__ void cp16(uint32_t dst, const void* src) {
    asm volatile("cp.async.cg.shared.global [%0], [%1], 16;" :: "r"(dst), "l"(src));
}
#define CP_COMMIT() asm volatile("cp.async.commit_group;")
#define CP_WAIT1()  asm volatile("cp.async.wait_group 1;")
__device__ __forceinline__ void ldsm4(uint32_t a, uint32_t& r0, uint32_t& r1, uint32_t& r2, uint32_t& r3) {
    asm volatile("ldmatrix.sync.aligned.m8n8.x4.shared.b16 {%0,%1,%2,%3}, [%4];"
        : "=r"(r0), "=r"(r1), "=r"(r2), "=r"(r3) : "r"(a));
}
__device__ __forceinline__ void mma16816(float* c, uint32_t a0, uint32_t a1, uint32_t a2, uint32_t a3,
                                         uint32_t b0, uint32_t b1) {
    asm volatile("mma.sync.aligned.m16n8k16.row.col.f32.bf16.bf16.f32 "
        "{%0,%1,%2,%3},{%4,%5,%6,%7},{%8,%9},{%0,%1,%2,%3};"
        : "+f"(c[0]), "+f"(c[1]), "+f"(c[2]), "+f"(c[3])
        : "r"(a0), "r"(a1), "r"(a2), "r"(a3), "r"(b0), "r"(b1));
}
__device__ __forceinline__ void ins3(float* td, int* ti, float v, int c) {
    if (v < td[2]) {
        td[2] = v; ti[2] = c;
        if (td[2] < td[1]) { float a = td[2]; td[2] = td[1]; td[1] = a; int b = ti[2]; ti[2] = ti[1]; ti[1] = b; }
        if (td[1] < td[0]) { float a = td[1]; td[1] = td[0]; td[0] = a; int b = ti[1]; ti[1] = ti[0]; ti[0] = b; }
    }
}

__global__ void conv_w(const float* __restrict__ W) {
    if (threadIdx.x < 8 && blockIdx.x < 1)
        for (int i = threadIdx.x; i < K_CODES; i += 8) g_counts[i] = 0;
    int warp = (blockIdx.x * blockDim.x + threadIdx.x) >> 5, lane = threadIdx.x & 31;
    if (warp >= K_CODES) return;
    const float* row = W + (size_t)warp * DDIM;
    float s = 0.f;
    for (int d = lane; d < DDIM; d += 32) {
        float v = row[d];
        s += v * v;
        g_whb[(size_t)warp * DDIM + d] = __float2bfloat16_rn(v);
    }
    for (int o = 16; o > 0; o >>= 1) s += __shfl_xor_sync(0xffffffffu, s, o);
    if (lane == 0) g_wsq[warp] = s;
}
__global__ void fsq_kernel(const float* __restrict__ x) {
    int b = blockIdx.x, t = threadIdx.x;
    const float* p = x + (size_t)b * DDIM * 256 + t;
    float s = 0.f;
    for (int d = 0; d < DDIM; d++) { float v = p[(size_t)d * 256]; s += v * v; }
    g_fsq[b * 256 + t] = s;
}
__global__ void conv_x(const float* __restrict__ x) {
    __shared__ float sh[64][65];
    int b = blockIdx.z, d0 = blockIdx.y * 64, t0 = blockIdx.x * 64, tid = threadIdx.x;
    #pragma unroll
    for (int i = 0; i < 16; i++) {
        int lin = i * 256 + tid, dd = lin >> 6, tt = lin & 63;
        sh[dd][tt] = x[((size_t)b * DDIM + d0 + dd) * 256 + t0 + tt];
    }
    __syncthreads();
    #pragma unroll
    for (int i = 0; i < 16; i++) {
        int lin = i * 256 + tid, nn = lin >> 6, dd = lin & 63;
        float v = sh[dd][nn];
        size_t o = (size_t)(b * 256 + t0 + nn) * DDIM + d0 + dd;
        g_xt[o] = v;
        g_xhb[o] = __float2bfloat16_rn(v);
    }
}

__global__ __launch_bounds__(512, 1)
void vq_main(const float* __restrict__ x, const float* __restrict__ W,
             float* __restrict__ out) {
    extern __shared__ char sm[];
    const uint32_t smb = smem_u32(sm);
    const int tid = threadIdx.x, wid = tid >> 5, lane = tid & 31;
    const int mw = wid >> 2, nw = wid & 3;       /* 4m x 4n warp grid */
    const int m0 = mw * 32;
    const int gr0 = blockIdx.x * BM;
    float* cd_s = (float*)(sm + SCD);
    int*   ci_s = (int*)(sm + SCI);
    float* wsq_s = (float*)(sm + SWSQ);
    float* fsq_s = (float*)(sm + SFSQ);
    int*   idx_s = (int*)(sm + SIDX);
    float* red_s = (float*)(sm + SRED);

    if (tid < BM) fsq_s[tid] = g_fsq[gr0 + tid];
    {   /* resident A tile: 128 x 512 bf16, stride 1040B */
        const int4* src = (const int4*)g_xhb;
        for (int i = tid; i < 8192; i += 512) {
            int row = i >> 6, seg = i & 63;
            *(int4*)(sm + SA + row * 1040 + seg * 16) = src[(size_t)(gr0 + row) * 64 + seg];
        }
    }
    const uint32_t aBase = smb + SA +
        (uint32_t)((m0 + ((lane >> 3) & 1) * 8 + (lane & 7)) * 1040 + ((lane >> 4) & 1) * 16);
    const uint32_t bOff =
        (uint32_t)(((((lane >> 4) & 1) * 8) + (lane & 7)) * 144 + ((lane >> 3) & 1) * 16);
    const int bc = tid >> 2, qq = tid & 3;
    const int lq = lane & 3;
    const int4* wsrc = (const int4*)g_whb;
    const uint32_t bDst = smb + SB + (uint32_t)(bc * 144 + qq * 32);

    float td[4][3]; int ti[4][3];
    #pragma unroll
    for (int rs = 0; rs < 4; rs++)
        #pragma unroll
        for (int s = 0; s < 3; s++) { td[rs][s] = INFINITY; ti[rs][s] = 0; }

    for (int p = 0; p < NPANEL; p++) {
        const int c0 = p * 128;
        __syncthreads();
        if (tid < 128) wsq_s[tid] = g_wsq[c0 + tid];
        const int4* srcRow = wsrc + (size_t)(c0 + bc) * 64 + qq * 2;
        #pragma unroll
        for (int j = 0; j < 2; j++) cp16(bDst + j * 16, srcRow + j);
        CP_COMMIT();
        #pragma unroll
        for (int j = 0; j < 2; j++) cp16(bDst + SBSTRIDE + j * 16, srcRow + 8 + j);
        CP_COMMIT();

        float acc[32];
        #pragma unroll
        for (int i = 0; i < 32; i++) acc[i] = 0.f;

        int st = 0, st2 = 2;
        for (int kc = 0; kc < NCH; kc++) {
            CP_WAIT1();
            __syncthreads();
            if (kc + 2 < NCH) {
                const int4* srcN = srcRow + (kc + 2) * 8;
                const uint32_t dstN = bDst + st2 * SBSTRIDE;
                #pragma unroll
                for (int j = 0; j < 2; j++) cp16(dstN + j * 16, srcN + j);
            }
            CP_COMMIT();
            const uint32_t bufB = smb + SB + st * SBSTRIDE;
            #pragma unroll
            for (int k16 = 0; k16 < 4; k16++) {
                uint32_t a[2][4], b[2][4];
                #pragma unroll
                for (int mf = 0; mf < 2; mf++)
                    ldsm4(aBase + mf * 16640 + kc * 128 + k16 * 32,
                          a[mf][0], a[mf][1], a[mf][2], a[mf][3]);
                #pragma unroll
                for (int n16 = 0; n16 < 2; n16++)
                    ldsm4(bufB + (nw * 2 + n16) * 2304 + bOff + k16 * 32,
                          b[n16][0], b[n16][1], b[n16][2], b[n16][3]);
                #pragma unroll
                for (int mf = 0; mf < 2; mf++)
                    #pragma unroll
                    for (int n16 = 0; n16 < 2; n16++) {
                        mma16816(acc + (mf * 2 + n16) * 8,
                                 a[mf][0], a[mf][1], a[mf][2], a[mf][3],
                                 b[n16][0], b[n16][1]);
                        mma16816(acc + (mf * 2 + n16) * 8 + 4,
                                 a[mf][0], a[mf][1], a[mf][2], a[mf][3],
                                 b[n16][2], b[n16][3]);
                    }
            }
            st = (st == 2) ? 0 : st + 1;
            st2 = (st2 == 2) ? 0 : st2 + 1;
        }
        /* in-register screening: per-thread top-3 over 4 row-slots */
        #pragma unroll
        for (int mf = 0; mf < 2; mf++)
            #pragma unroll
            for (int n16 = 0; n16 < 2; n16++)
                #pragma unroll
                for (int pp = 0; pp < 2; pp++) {
                    const int c = nw * 32 + n16 * 16 + pp * 8 + lq * 2;
                    const float w0 = wsq_s[c], w1 = wsq_s[c + 1];
                    const int code = c0 + c;
                    const int qi = (mf * 2 + n16) * 8 + pp * 4;
                    ins3(td[mf * 2 + 0], ti[mf * 2 + 0], fmaf(-2.f, acc[qi + 0], w0), code);
                    ins3(td[mf * 2 + 0], ti[mf * 2 + 0], fmaf(-2.f, acc[qi + 1], w1), code + 1);
                    ins3(td[mf * 2 + 1], ti[mf * 2 + 1], fmaf(-2.f, acc[qi + 2], w0), code);
                    ins3(td[mf * 2 + 1], ti[mf * 2 + 1], fmaf(-2.f, acc[qi + 3], w1), code + 1);
                }
    }
    __syncthreads();     /* B ring dead -> candidate store */
    {   /* dump 48 candidates per row: (nw*4+lq)*3 slots */
        const int slot = (nw * 4 + lq) * 3;
        #pragma unroll
        for (int mf = 0; mf < 2; mf++)
            #pragma unroll
            for (int hl = 0; hl < 2; hl++) {
                const int row = m0 + mf * 16 + hl * 8 + (lane >> 2);
                #pragma unroll
                for (int s = 0; s < 3; s++) {
                    cd_s[row * 48 + slot + s] = td[mf * 2 + hl][s];
                    ci_s[row * 48 + slot + s] = ti[mf * 2 + hl][s];
                }
            }
    }
    __syncthreads();

    /* prune to approx-top-12 (lex) per row, store into slots [36,48) */
    if (tid < BM) {
        float pd[12]; int pi[12];
        #pragma unroll
        for (int s = 0; s < 12; s++) { pd[s] = INFINITY; pi[s] = 0x7fffffff; }
        for (int s = 0; s < 48; s++) {
            float d = cd_s[tid * 48 + s]; int c = ci_s[tid * 48 + s];
            if (d < pd[11] || (d == pd[11] && c < pi[11])) {
                pd[11] = d; pi[11] = c;
                #pragma unroll
                for (int k = 11; k > 0; k--)
                    if (pd[k] < pd[k - 1] || (pd[k] == pd[k - 1] && pi[k] < pi[k - 1])) {
                        float t1 = pd[k]; pd[k] = pd[k - 1]; pd[k - 1] = t1;
                        int t2 = pi[k]; pi[k] = pi[k - 1]; pi[k - 1] = t2;
                    }
            }
        }
        #pragma unroll
        for (int s = 0; s < 12; s++) {
            cd_s[tid * 48 + 36 + s] = pd[s]; ci_s[tid * 48 + 36 + s] = pi[s];
        }
    }
    __syncthreads();

    /* exact rescore (R1 FFMA chain): 128 x 12 */
    #pragma unroll 1
    for (int q = 0; q < 3; q++) {
        const int pair = q * 512 + tid;
        const int r = pair / 12, sl = pair - r * 12;
        const int ci = ci_s[r * 48 + 36 + sl];
        const float4* wp = (const float4*)(W + (size_t)ci * DDIM);
        const float4* xp = (const float4*)(g_xt + (size_t)(gr0 + r) * DDIM);
        float s = 0.f;
        #pragma unroll 8
        for (int d4 = 0; d4 < 128; d4++) {
            float4 a = xp[d4], b = wp[d4];
            s = fmaf(a.x, b.x, s); s = fmaf(a.y, b.y, s);
            s = fmaf(a.z, b.z, s); s = fmaf(a.w, b.w, s);
        }
        cd_s[r * 48 + 36 + sl] =
            __fadd_rn(__fadd_rn(fsq_s[r], g_wsq[ci]), -__fmul_rn(2.0f, s));
    }
    __syncthreads();

    if (tid < BM) {
        float b0 = INFINITY, b1 = INFINITY, b2 = INFINITY;
        int i0 = 0x7fffffff, i1 = 0x7fffffff, i2 = 0x7fffffff;
        #pragma unroll
        for (int s = 0; s < 12; s++) {
            float d = cd_s[tid * 48 + 36 + s]; int c = ci_s[tid * 48 + 36 + s];
            if (d < b0 || (d == b0 && c < i0)) {
                b2 = b1; i2 = i1; b1 = b0; i1 = i0; b0 = d; i0 = c;
            } else if (d < b1 || (d == b1 && c < i1)) {
                b2 = b1; i2 = i1; b1 = d; i1 = c;
            } else if (d < b2 || (d == b2 && c < i2)) {
                b2 = d; i2 = c;
            }
        }
        idx_s[tid * 3 + 0] = i0; idx_s[tid * 3 + 1] = i1; idx_s[tid * 3 + 2] = i2;
        atomicAdd(&g_counts[i0], 1);
        atomicAdd(&g_counts[i1], 1);
        atomicAdd(&g_counts[i2], 1);
        out[OUT_IDX + gr0 + tid] = (float)i2;
    }
    __syncthreads();

    /* quantized output + MSE */
    const int bq = gr0 >> 8, t0 = gr0 & 255;
    float* q_s = (float*)(sm + SA);
    float mse = 0.f;
    const int r = tid & 127, dh = tid >> 7;   /* 0..3 */
    const int j0 = idx_s[r * 3 + 0], j1 = idx_s[r * 3 + 1], j2 = idx_s[r * 3 + 2];
    for (int dc = 0; dc < 16; dc++) {
        const int d0 = dc * 32 + dh * 8;
        #pragma unroll
        for (int q4 = 0; q4 < 2; q4++) {
            float4 a = *(const float4*)(W + (size_t)j0 * DDIM + d0 + q4 * 4);
            float4 bb = *(const float4*)(W + (size_t)j1 * DDIM + d0 + q4 * 4);
            float4 cc = *(const float4*)(W + (size_t)j2 * DDIM + d0 + q4 * 4);
            int dl = dh * 8 + q4 * 4;
            q_s[(dl + 0) * 128 + r] = (a.x + bb.x + cc.x) * (1.0f / 3.0f);
            q_s[(dl + 1) * 128 + r] = (a.y + bb.y + cc.y) * (1.0f / 3.0f);
            q_s[(dl + 2) * 128 + r] = (a.z + bb.z + cc.z) * (1.0f / 3.0f);
            q_s[(dl + 3) * 128 + r] = (a.w + bb.w + cc.w) * (1.0f / 3.0f);
        }
        __syncthreads();
        #pragma unroll
        for (int i = 0; i < 8; i++) {
            int lin = i * 512 + tid, dl = lin >> 7, rr = lin & 127;
            int d = dc * 32 + dl;
            size_t go = (size_t)(bq * DDIM + d) * 256 + t0 + rr;
            float qv = q_s[dl * 128 + rr];
            out[OUT_Q + go] = qv;
            float df = qv - x[go];
            mse += df * df;
        }
        __syncthreads();
    }
    for (int o = 16; o > 0; o >>= 1) mse += __shfl_xor_sync(0xffffffffu, mse, o);
    if (lane == 0) red_s[wid] = mse;
    __syncthreads();
    if (tid == 0) {
        float s = 0.f;
        #pragma unroll
        for (int i = 0; i < 16; i++) s += red_s[i];
        g_partials[blockIdx.x] = s;
    }
}

__global__ void finalize_kernel(float* __restrict__ out) {
    __shared__ float red[256];
    int tid = threadIdx.x;
    red[tid] = (tid < 128) ? g_partials[tid] : 0.f;
    __syncthreads();
    for (int s = 128; s > 0; s >>= 1) {
        if (tid < s) red[tid] += red[tid + s];
        __syncthreads();
    }
    if (tid == 0) out[OUT_LOSS] = 1.25f * (red[0] / (float)QN);
    __syncthreads();
    float e = 0.f;
    for (int k = tid; k < K_CODES; k += 256) {
        float pr = (float)g_counts[k] * (1.0f / (float)N_ROWS);
        e += pr * logf(pr + 1e-10f);
    }
    red[tid] = e;
    __syncthreads();
    for (int s = 128; s > 0; s >>= 1) {
        if (tid < s) red[tid] += red[tid + s];
        __syncthreads();
    }
    if (tid == 0) out[OUT_PERP] = expf(-red[0]);
}

extern "C" void kernel_launch(void* const* d_in, const int* in_sizes, int n_in,
                              void* d_out, int out_size) {
    const float* x = (const float*)d_in[0];
    const float* W = (const float*)d_in[1];
    float* out = (float*)d_out;
    (void)in_sizes; (void)n_in; (void)out_size;
    cudaFuncSetAttribute(vq_main, cudaFuncAttributeMaxDynamicSharedMemorySize, SMEM_BYTES);
    conv_w<<<256, 256>>>(W);
    fsq_kernel<<<64, 256>>>(x);
    conv_x<<<dim3(4, 8, 64), 256>>>(x);
    vq_main<<<128, 512, SMEM_BYTES>>>(x, W, out);
    finalize_kernel<<<1, 256>>>(out);
}